// round 16
// baseline (speedup 1.0000x reference)
#include <cuda_runtime.h>
#include <cuda_bf16.h>
#include <cmath>
#include <cstdint>

// ---------------- problem constants ----------------
static constexpr int B_   = 512;
static constexpr int T_   = 12;
static constexpr int E_   = 1024;
static constexpr int NH_  = 8;
static constexpr int HS_  = 128;
static constexpr int H_   = 1024;
static constexpr int G4_  = 4096;
static constexpr int BT_  = B_ * T_;        // 6144

// ---------------- scratch (device globals; no allocation) ----------------
__device__ float d_xn [BT_ * (size_t)E_];
__device__ float d_xc [BT_ * (size_t)E_];
__device__ float d_x1 [BT_ * (size_t)E_];
__device__ float d_y  [BT_ * (size_t)E_];
// bf16 operands
__device__ __nv_bfloat16 d_gxh [BT_ * (size_t)G4_];
__device__ __nv_bfloat16 d_hnh [BT_ * (size_t)H_];
__device__ __nv_bfloat16 d_uh  [BT_ * (size_t)H_];
// fp8 quad-packed operands for gx GEMM: word = e4m3 x4 along k
__device__ uint32_t d_xn2q[(size_t)BT_ * 256];        // [m][k/4]
__device__ uint32_t d_Wq  [(size_t)256 * G4_];        // [k/4][n], weights pre-scaled x16
// pair-packed bf16 weights
__device__ uint32_t d_downp[(size_t)512 * E_];
__device__ uint32_t d_Wpair[(size_t)512 * 2048];
__device__ uint32_t d_Rgp  [(size_t)NH_ * 64 * 512];

// ---------------- helpers ----------------
__device__ __forceinline__ float gelu_exact(float x) {
    return 0.5f * x * (1.0f + erff(x * 0.70710678118654752440f));
}
__device__ __forceinline__ float sigmoidf_(float x) {
    return 1.0f / (1.0f + expf(-x));
}
__device__ __forceinline__ void cp_async16(uint32_t saddr, const void* g) {
    asm volatile("cp.async.cg.shared.global [%0], [%1], 16;" :: "r"(saddr), "l"(g));
}
__device__ __forceinline__ void mma_bf16(float* acc, uint32_t a0, uint32_t a1,
                                         uint32_t a2, uint32_t a3,
                                         uint32_t b0, uint32_t b1) {
    asm volatile(
        "mma.sync.aligned.m16n8k16.row.col.f32.bf16.bf16.f32 "
        "{%0,%1,%2,%3}, {%4,%5,%6,%7}, {%8,%9}, {%0,%1,%2,%3};"
        : "+f"(acc[0]), "+f"(acc[1]), "+f"(acc[2]), "+f"(acc[3])
        : "r"(a0), "r"(a1), "r"(a2), "r"(a3), "r"(b0), "r"(b1));
}
__device__ __forceinline__ void mma_fp8(float* acc, uint32_t a0, uint32_t a1,
                                        uint32_t a2, uint32_t a3,
                                        uint32_t b0, uint32_t b1) {
    asm volatile(
        "mma.sync.aligned.m16n8k32.row.col.f32.e4m3.e4m3.f32 "
        "{%0,%1,%2,%3}, {%4,%5,%6,%7}, {%8,%9}, {%0,%1,%2,%3};"
        : "+f"(acc[0]), "+f"(acc[1]), "+f"(acc[2]), "+f"(acc[3])
        : "r"(a0), "r"(a1), "r"(a2), "r"(a3), "r"(b0), "r"(b1));
}
__device__ __forceinline__ void ldsm_x4(uint32_t* r, uint32_t saddr) {
    asm volatile("ldmatrix.sync.aligned.m8n8.x4.shared.b16 {%0,%1,%2,%3}, [%4];"
        : "=r"(r[0]), "=r"(r[1]), "=r"(r[2]), "=r"(r[3]) : "r"(saddr));
}
__device__ __forceinline__ uint32_t pack_e4m3x4(float v0, float v1, float v2, float v3) {
    uint16_t lo, hi;
    asm("cvt.rn.satfinite.e4m3x2.f32 %0, %1, %2;" : "=h"(lo) : "f"(v1), "f"(v0));
    asm("cvt.rn.satfinite.e4m3x2.f32 %0, %1, %2;" : "=h"(hi) : "f"(v3), "f"(v2));
    return (uint32_t)lo | ((uint32_t)hi << 16);
}
__device__ __forceinline__ void warp_reduce_2(float& s, float& ss) {
    #pragma unroll
    for (int o = 16; o; o >>= 1) {
        s  += __shfl_xor_sync(0xffffffffu, s,  o);
        ss += __shfl_xor_sync(0xffffffffu, ss, o);
    }
}

// ---------------- weight packs ----------------
__global__ void pack_all(const float* __restrict__ downw,
                         const float* __restrict__ wl,
                         const float* __restrict__ wr) {
    int z = blockIdx.z;
    int kp = blockIdx.y;
    int n = blockIdx.x * 256 + threadIdx.x;
    if (z == 0) {
        __nv_bfloat162 h = __floats2bfloat162_rn(downw[(size_t)(2 * kp) * 1024 + n],
                                                 downw[(size_t)(2 * kp + 1) * 1024 + n]);
        d_downp[(size_t)kp * 1024 + n] = *reinterpret_cast<uint32_t*>(&h);
    } else {
        __nv_bfloat162 hl = __floats2bfloat162_rn(wl[(size_t)(2 * kp) * 1024 + n],
                                                  wl[(size_t)(2 * kp + 1) * 1024 + n]);
        __nv_bfloat162 hr = __floats2bfloat162_rn(wr[(size_t)(2 * kp) * 1024 + n],
                                                  wr[(size_t)(2 * kp + 1) * 1024 + n]);
        d_Wpair[(size_t)kp * 2048 + 2 * n]     = *reinterpret_cast<uint32_t*>(&hl);
        d_Wpair[(size_t)kp * 2048 + 2 * n + 1] = *reinterpret_cast<uint32_t*>(&hr);
    }
}
// Wq[kq][n] = e4m3x4(16 * Wg[4kq+0..3][n])
__global__ void pack_wq(const float* __restrict__ Wg) {
    int n = blockIdx.x * 256 + threadIdx.x;
    int kq = blockIdx.y;
    float w0 = Wg[(size_t)(4 * kq)     * 4096 + n] * 16.f;
    float w1 = Wg[(size_t)(4 * kq + 1) * 4096 + n] * 16.f;
    float w2 = Wg[(size_t)(4 * kq + 2) * 4096 + n] * 16.f;
    float w3 = Wg[(size_t)(4 * kq + 3) * 4096 + n] * 16.f;
    d_Wq[(size_t)kq * 4096 + n] = pack_e4m3x4(w0, w1, w2, w3);
}
__global__ __launch_bounds__(256) void pack_rg(const float* __restrict__ Rg) {
    __shared__ float tile[32][129];
    int head = blockIdx.x;
    int g0 = blockIdx.y * 32;
    int tid = threadIdx.x;
    #pragma unroll
    for (int i = 0; i < 16; i++) {
        int e = i * 256 + tid;
        int r = e >> 7, c = e & 127;
        tile[r][c] = Rg[((size_t)(head * 512 + g0 + r)) * 128 + c];
    }
    __syncthreads();
    #pragma unroll
    for (int i = 0; i < 8; i++) {
        int e = i * 256 + tid;
        int kp = e >> 5, gl = e & 31;
        __nv_bfloat162 h = __floats2bfloat162_rn(tile[gl][2 * kp], tile[gl][2 * kp + 1]);
        d_Rgp[((size_t)(head * 64 + kp)) * 512 + g0 + gl] =
            *reinterpret_cast<uint32_t*>(&h);
    }
}

// ---------------- fused front: LN(x) -> fc1 conv -> fc2 -> LN -> fp8 quad ----------------
__global__ __launch_bounds__(384) void fused_front(
    const float* __restrict__ x,
    const float* __restrict__ ln_g, const float* __restrict__ ln_b,
    const float* __restrict__ w1g, const float* __restrict__ b1g,
    const float* __restrict__ w2g, const float* __restrict__ b2g,
    const float* __restrict__ xlg, const float* __restrict__ xlb) {
    extern __shared__ float sm[];
    float* sxn = sm;
    float* sxc = sxn + 12 * 1032;
    float* sx1 = sxc + 12 * 1024;
    float* sw1 = sx1 + 12 * 1024;
    float* sw2 = sw1 + 432;
    float* sb1 = sw2 + 144;
    float* sb2 = sb1 + 12;
    int b = blockIdx.x, tid = threadIdx.x, w = tid >> 5, lane = tid & 31;

    for (int i = tid; i < 432; i += 384) sw1[i] = w1g[i];
    if (tid < 144) sw2[tid] = w2g[tid];
    if (tid < 12) { sb1[tid] = b1g[tid]; sb2[tid] = b2g[tid]; }
    if (lane == 0) { sxn[w * 1032] = 0.f; sxn[w * 1032 + 1025] = 0.f; }

    size_t rbase = ((size_t)b * 12 + w) * 1024;
    const float* xr = x + rbase;
    float4 vals[8];
    float s = 0.f, ss = 0.f;
    #pragma unroll
    for (int j = 0; j < 8; j++) {
        float4 v = *reinterpret_cast<const float4*>(xr + lane * 4 + j * 128);
        vals[j] = v;
        s  += v.x + v.y + v.z + v.w;
        ss += v.x*v.x + v.y*v.y + v.z*v.z + v.w*v.w;
    }
    warp_reduce_2(s, ss);
    float mu = s * (1.0f / 1024.0f);
    float rstd = rsqrtf(ss * (1.0f / 1024.0f) - mu * mu + 1e-5f);
    #pragma unroll
    for (int j = 0; j < 8; j++) {
        int idx = lane * 4 + j * 128;
        float4 g = *reinterpret_cast<const float4*>(ln_g + idx);
        float4 bb = *reinterpret_cast<const float4*>(ln_b + idx);
        float4 v = vals[j], o;
        o.x = (v.x - mu) * rstd * g.x + bb.x;
        o.y = (v.y - mu) * rstd * g.y + bb.y;
        o.z = (v.z - mu) * rstd * g.z + bb.z;
        o.w = (v.w - mu) * rstd * g.w + bb.w;
        sxn[w * 1032 + 1 + idx] = o.x; sxn[w * 1032 + 2 + idx] = o.y;
        sxn[w * 1032 + 3 + idx] = o.z; sxn[w * 1032 + 4 + idx] = o.w;
        *reinterpret_cast<float4*>(d_xn + rbase + idx) = o;
    }
    __syncthreads();

    {   int o = w;
        float wl[36];
        #pragma unroll
        for (int i = 0; i < 36; i++) wl[i] = sw1[o * 36 + i];
        float bo = sb1[o];
        for (int j = 0; j < 32; j++) {
            int l = lane + j * 32;
            float a = bo;
            #pragma unroll
            for (int c = 0; c < 12; c++) {
                a += wl[c*3]   * sxn[c * 1032 + l]
                   + wl[c*3+1] * sxn[c * 1032 + l + 1]
                   + wl[c*3+2] * sxn[c * 1032 + l + 2];
            }
            sxc[o * 1024 + l] = a;
            d_xc[rbase + l] = a;
        }
    }
    __syncthreads();

    {   int o = w;
        float wl[12];
        #pragma unroll
        for (int c = 0; c < 12; c++) wl[c] = sw2[o * 12 + c];
        float bo = sb2[o];
        for (int j = 0; j < 32; j++) {
            int l = lane + j * 32;
            float a = bo;
            #pragma unroll
            for (int c = 0; c < 12; c++) a += wl[c] * sxc[c * 1024 + l];
            sx1[o * 1024 + l] = a;
            d_x1[rbase + l] = a;
        }
    }
    __syncthreads();

    s = 0.f; ss = 0.f;
    #pragma unroll
    for (int j = 0; j < 8; j++) {
        float4 v = *reinterpret_cast<const float4*>(sx1 + w * 1024 + lane * 4 + j * 128);
        vals[j] = v;
        s  += v.x + v.y + v.z + v.w;
        ss += v.x*v.x + v.y*v.y + v.z*v.z + v.w*v.w;
    }
    warp_reduce_2(s, ss);
    mu = s * (1.0f / 1024.0f);
    rstd = rsqrtf(ss * (1.0f / 1024.0f) - mu * mu + 1e-5f);
    #pragma unroll
    for (int j = 0; j < 8; j++) {
        int idx = lane * 4 + j * 128;
        float4 g = *reinterpret_cast<const float4*>(xlg + idx);
        float4 bb = *reinterpret_cast<const float4*>(xlb + idx);
        float4 v = vals[j];
        float o0 = (v.x - mu) * rstd * g.x + bb.x;
        float o1 = (v.y - mu) * rstd * g.y + bb.y;
        float o2 = (v.z - mu) * rstd * g.z + bb.z;
        float o3 = (v.w - mu) * rstd * g.w + bb.w;
        d_xn2q[(size_t)(b * 12 + w) * 256 + lane + j * 32] =
            pack_e4m3x4(o0, o1, o2, o3);
    }
}

// ---------------- fused tail: all-fp32, 3 chunks of 16 z-rows ----------------
__global__ __launch_bounds__(512) void fused_tail(
    const float* __restrict__ w1g, const float* __restrict__ b1g,
    const float* __restrict__ w2g, const float* __restrict__ b2g,
    const float* __restrict__ ln_g, const float* __restrict__ ln_b,
    float* __restrict__ out) {
    extern __shared__ float sm[];
    float* sy  = sm;
    float* szf = sy + 12 * 1032;
    float* sw1 = szf + 16 * 1032;
    float* sw2 = sw1 + 1728;
    float* sb1 = sw2 + 1728;
    float* sb2 = sb1 + 48;
    int b = blockIdx.x, tid = threadIdx.x, w = tid >> 5, lane = tid & 31;

    for (int i = tid; i < 12 * 256; i += 512) {
        int c = i >> 8, q = (i & 255) * 4;
        float4 v = *reinterpret_cast<const float4*>(d_y + ((size_t)b * 12 + c) * 1024 + q);
        sy[c * 1032 + 1 + q]     = v.x;
        sy[c * 1032 + 1 + q + 1] = v.y;
        sy[c * 1032 + 1 + q + 2] = v.z;
        sy[c * 1032 + 1 + q + 3] = v.w;
    }
    if (tid < 12) { sy[tid * 1032] = 0.f; sy[tid * 1032 + 1025] = 0.f; }
    if (tid < 16) { szf[tid * 1032] = 0.f; szf[tid * 1032 + 1025] = 0.f; }
    for (int i = tid; i < 1728; i += 512) {
        sw1[i] = w1g[i];
        int o = i / 144, rem = i % 144;
        int c = rem / 3, k = rem % 3;
        sw2[c * 36 + o * 3 + k] = w2g[i];
    }
    if (tid < 48) sb1[tid] = b1g[tid];
    if (tid < 12) sb2[tid] = b2g[tid];
    __syncthreads();

    int l2 = tid * 2;
    float acc0[12], acc1[12];
    #pragma unroll
    for (int o = 0; o < 12; o++) { acc0[o] = 0.f; acc1[o] = 0.f; }

    for (int cc = 0; cc < 3; cc++) {
        int o = cc * 16 + w;
        float wl[36];
        #pragma unroll
        for (int i = 0; i < 36; i++) wl[i] = sw1[o * 36 + i];
        float bo = sb1[o];
        float vbuf[32];
        float s = 0.f, ss = 0.f;
        #pragma unroll 4
        for (int j = 0; j < 32; j++) {
            int l = lane + j * 32;
            float a = bo;
            #pragma unroll
            for (int c = 0; c < 12; c++) {
                a += wl[c*3]   * sy[c * 1032 + l]
                   + wl[c*3+1] * sy[c * 1032 + l + 1]
                   + wl[c*3+2] * sy[c * 1032 + l + 2];
            }
            float v = gelu_exact(a);
            vbuf[j] = v;
            s += v; ss += v * v;
        }
        warp_reduce_2(s, ss);
        float mu = s * (1.0f / 1024.0f);
        float rstd = rsqrtf(ss * (1.0f / 1024.0f) - mu * mu + 1e-5f);
        #pragma unroll 4
        for (int j = 0; j < 32; j++) {
            int l = lane + j * 32;
            szf[w * 1032 + 1 + l] =
                (vbuf[j] - mu) * rstd * __ldg(ln_g + l) + __ldg(ln_b + l);
        }
        __syncthreads();

        for (int c16 = 0; c16 < 16; c16++) {
            int c = cc * 16 + c16;
            const float* zr = szf + c16 * 1032 + l2;
            float2 p0 = *reinterpret_cast<const float2*>(zr);
            float2 p1 = *reinterpret_cast<const float2*>(zr + 2);
            float h0 = p0.x, h1 = p0.y, h2 = p1.x, h3 = p1.y;
            const float* wr = sw2 + c * 36;
            #pragma unroll
            for (int o2 = 0; o2 < 12; o2++) {
                float w0 = wr[o2*3], w1 = wr[o2*3+1], w2v = wr[o2*3+2];
                acc0[o2] += w0 * h0 + w1 * h1 + w2v * h2;
                acc1[o2] += w0 * h1 + w1 * h2 + w2v * h3;
            }
        }
        __syncthreads();
    }

    #pragma unroll
    for (int o = 0; o < 12; o++) {
        size_t idx = ((size_t)b * 12 + o) * 1024 + l2;
        float2 sk = *reinterpret_cast<const float2*>(d_xn + idx);
        float2 ov;
        ov.x = acc0[o] + sb2[o] + sk.x;
        ov.y = acc1[o] + sb2[o] + sk.y;
        *reinterpret_cast<float2*>(out + idx) = ov;
    }
}

// ---------------- fp8 tensor-core GEMM for gx: 3-stage cp.async + ldmatrix A ----------------
// C[6144,4096] = (A_e4m3 @ (16*W)_e4m3) / 16 + bias -> bf16. K=1024, BK=64.
__global__ __launch_bounds__(256) void gemm_fp8_gx(const float* __restrict__ bias) {
    __shared__ uint32_t As[3][128 * 20];    // [r][16 words + pad 4]
    __shared__ uint32_t Bs[3][16 * 136];    // [kq][128 cols + pad]
    int tid = threadIdx.x;
    int warp = tid >> 5, lane = tid & 31;
    int g = lane >> 2, tg = lane & 3;
    int warpM = warp >> 2, warpN = warp & 3;
    int row0 = blockIdx.y * 128, col0 = blockIdx.x * 128;

    uint32_t asb = (uint32_t)__cvta_generic_to_shared(&As[0][0]);
    uint32_t bsb = (uint32_t)__cvta_generic_to_shared(&Bs[0][0]);

    float acc[4][4][4];
    #pragma unroll
    for (int m = 0; m < 4; m++)
        #pragma unroll
        for (int n = 0; n < 4; n++)
            #pragma unroll
            for (int q = 0; q < 4; q++) acc[m][n][q] = 0.f;

    const int nt = 16;   // K/64

    auto load_tile = [&](int it, int buf) {
        int kq0 = it << 4;   // 16 quad-words per BK=64
        #pragma unroll
        for (int i = 0; i < 2; i++) {
            int e = i * 256 + tid;
            int r = e >> 2, ch = e & 3;
            cp_async16(asb + (uint32_t)(buf * 128 * 20 + r * 20 + ch * 4) * 4,
                       d_xn2q + (size_t)(row0 + r) * 256 + kq0 + ch * 4);
        }
        #pragma unroll
        for (int i = 0; i < 2; i++) {
            int e = i * 256 + tid;
            int kp = e >> 5, c = (e & 31) * 4;
            cp_async16(bsb + (uint32_t)(buf * 16 * 136 + kp * 136 + c) * 4,
                       d_Wq + (size_t)(kq0 + kp) * 4096 + col0 + c);
        }
        asm volatile("cp.async.commit_group;");
    };

    load_tile(0, 0);
    load_tile(1, 1);

    int arow = warpM * 64;
    int bcol = warpN * 32 + g;
    int lseg = lane >> 3;
    int a_row = (lseg & 1) * 8 + (lane & 7);
    int a_kw  = (lseg >> 1) * 4;

    for (int it = 0; it < nt; it++) {
        int buf = it - (it / 3) * 3;
        asm volatile("cp.async.wait_group 1;");
        __syncthreads();
        if (it + 2 < nt) {
            int buf2 = (it + 2) - ((it + 2) / 3) * 3;
            load_tile(it + 2, buf2);
        } else {
            asm volatile("cp.async.commit_group;");
        }
        uint32_t a_base = asb + (uint32_t)(buf * 128 * 20) * 4;
        const uint32_t* Bb = &Bs[buf][0];
        #pragma unroll
        for (int s = 0; s < 2; s++) {       // two k32 steps per BK=64
            uint32_t af[4][4];
            #pragma unroll
            for (int m = 0; m < 4; m++) {
                uint32_t sa = a_base +
                    (uint32_t)((arow + m * 16 + a_row) * 20 + s * 8 + a_kw) * 4;
                ldsm_x4(af[m], sa);
            }
            uint32_t bf[4][2];
            #pragma unroll
            for (int n = 0; n < 4; n++) {
                int c = bcol + n * 8;
                bf[n][0] = Bb[(s * 8 + tg)     * 136 + c];
                bf[n][1] = Bb[(s * 8 + tg + 4) * 136 + c];
            }
            #pragma unroll
            for (int m = 0; m < 4; m++)
                #pragma unroll
                for (int n = 0; n < 4; n++)
                    mma_fp8(acc[m][n], af[m][0], af[m][1], af[m][2], af[m][3],
                            bf[n][0], bf[n][1]);
        }
    }

    __syncthreads();
    #pragma unroll
    for (int m = 0; m < 4; m++) {
        int r = row0 + warpM * 64 + m * 16 + g;
        #pragma unroll
        for (int n = 0; n < 4; n++) {
            int c = col0 + warpN * 32 + n * 8 + 2 * tg;
            #pragma unroll
            for (int half = 0; half < 2; half++) {
                int rr = r + half * 8;
                size_t i0 = (size_t)rr * 4096 + c;
                float v0 = acc[m][n][half * 2 + 0] * 0.0625f + bias[c];
                float v1 = acc[m][n][half * 2 + 1] * 0.0625f + bias[c + 1];
                __nv_bfloat162 hh = __floats2bfloat162_rn(v0, v1);
                *reinterpret_cast<uint32_t*>(d_gxh + i0) =
                    *reinterpret_cast<uint32_t*>(&hh);
            }
        }
    }
}

// ---------------- mma.sync bf16 GEMM (pair + down) ----------------
template<int MODE>
__global__ __launch_bounds__(256) void gemm_bf16(int N, int K,
                                                 const __nv_bfloat16* __restrict__ A,
                                                 const uint32_t* __restrict__ Bp,
                                                 const float* __restrict__ bias,
                                                 const float* __restrict__ aux0,
                                                 const float* __restrict__ aux1,
                                                 const float* __restrict__ aux2,
                                                 void* __restrict__ Cout) {
    __shared__ uint32_t As[3][128 * 20];
    __shared__ uint32_t Bs[3][16 * 136];
    int tid = threadIdx.x;
    int warp = tid >> 5, lane = tid & 31;
    int g = lane >> 2, tg = lane & 3;
    int warpM = warp >> 2, warpN = warp & 3;
    int row0 = blockIdx.y * 128, col0 = blockIdx.x * 128;

    uint32_t asb = (uint32_t)__cvta_generic_to_shared(&As[0][0]);
    uint32_t bsb = (uint32_t)__cvta_generic_to_shared(&Bs[0][0]);

    float acc[4][4][4];
    #pragma unroll
    for (int m = 0; m < 4; m++)
        #pragma unroll
        for (int n = 0; n < 4; n++)
            #pragma unroll
            for (int q = 0; q < 4; q++) acc[m][n][q] = 0.f;

    const int nt = K >> 5;

    auto load_tile = [&](int it, int buf) {
        int k0 = it << 5;
        int kp0 = it << 4;
        #pragma unroll
        for (int i = 0; i < 2; i++) {
            int e = i * 256 + tid;
            int r = e >> 2, ch = e & 3;
            cp_async16(asb + (uint32_t)(buf * 128 * 20 + r * 20 + ch * 4) * 4,
                       A + (size_t)(row0 + r) * K + k0 + ch * 8);
        }
        #pragma unroll
        for (int i = 0; i < 2; i++) {
            int e = i * 256 + tid;
            int kp = e >> 5, c = (e & 31) * 4;
            cp_async16(bsb + (uint32_t)(buf * 16 * 136 + kp * 136 + c) * 4,
                       Bp + (size_t)(kp0 + kp) * N + col0 + c);
        }
        asm volatile("cp.async.commit_group;");
    };

    load_tile(0, 0);
    load_tile(1, 1);

    int arow = warpM * 64;
    int bcol = warpN * 32 + g;
    int lseg = lane >> 3;
    int a_row = (lseg & 1) * 8 + (lane & 7);
    int a_kw  = (lseg >> 1) * 4;

    for (int it = 0; it < nt; it++) {
        int buf = it - (it / 3) * 3;
        asm volatile("cp.async.wait_group 1;");
        __syncthreads();
        if (it + 2 < nt) {
            int buf2 = (it + 2) - ((it + 2) / 3) * 3;
            load_tile(it + 2, buf2);
        } else {
            asm volatile("cp.async.commit_group;");
        }
        uint32_t a_base = asb + (uint32_t)(buf * 128 * 20) * 4;
        const uint32_t* Bb = &Bs[buf][0];
        #pragma unroll
        for (int s = 0; s < 2; s++) {
            uint32_t af[4][4];
            #pragma unroll
            for (int m = 0; m < 4; m++) {
                uint32_t sa = a_base +
                    (uint32_t)((arow + m * 16 + a_row) * 20 + s * 8 + a_kw) * 4;
                ldsm_x4(af[m], sa);
            }
            uint32_t bf[4][2];
            #pragma unroll
            for (int n = 0; n < 4; n++) {
                int c = bcol + n * 8;
                bf[n][0] = Bb[(s * 8 + tg)     * 136 + c];
                bf[n][1] = Bb[(s * 8 + tg + 4) * 136 + c];
            }
            #pragma unroll
            for (int m = 0; m < 4; m++)
                #pragma unroll
                for (int n = 0; n < 4; n++)
                    mma_bf16(acc[m][n], af[m][0], af[m][1], af[m][2], af[m][3],
                             bf[n][0], bf[n][1]);
        }
    }

    __syncthreads();
    #pragma unroll
    for (int m = 0; m < 4; m++) {
        int r = row0 + warpM * 64 + m * 16 + g;
        #pragma unroll
        for (int n = 0; n < 4; n++) {
            int c = col0 + warpN * 32 + n * 8 + 2 * tg;
            #pragma unroll
            for (int half = 0; half < 2; half++) {
                int rr = r + half * 8;
                float a0 = acc[m][n][half * 2 + 0];
                float a1 = acc[m][n][half * 2 + 1];
                if (MODE == 3) {
                    int j = c >> 1;
                    float l  = a0 + bias[j];
                    float rv = a1 + aux1[j];
                    ((__nv_bfloat16*)Cout)[(size_t)rr * (N >> 1) + j] =
                        __float2bfloat16_rn(gelu_exact(l) * rv);
                } else {
                    size_t i0 = (size_t)rr * N + c;
                    float v0 = a0 + bias[c];
                    float v1 = a1 + bias[c + 1];
                    if (MODE == 2) {
                        float x0 = aux0[i0], x1v = aux0[i0 + 1];
                        v0 = x0  * sigmoidf_(x0)  * (v0 + aux1[i0])     + aux2[i0];
                        v1 = x1v * sigmoidf_(x1v) * (v1 + aux1[i0 + 1]) + aux2[i0 + 1];
                    }
                    *reinterpret_cast<float2*>((float*)Cout + i0) = make_float2(v0, v1);
                }
            }
        }
    }
}

// ---------------- sLSTM recurrence v4: fused GroupNorm -> d_hnh ----------------
__global__ __launch_bounds__(256) void slstm_rec4(const float* __restrict__ gng,
                                                  const float* __restrict__ gnb) {
    extern __shared__ uint32_t smw[];
    uint32_t* sBp = smw;
    float* s_rec = (float*)(smw + 64 * 520);
    uint32_t* sh_w = (uint32_t*)(s_rec + 32 * 516);
    float* gn_part = (float*)(sh_w + 32 * 68);
    __nv_bfloat16* sh_h = (__nv_bfloat16*)sh_w;

    int head = blockIdx.x >> 4;
    int b0 = (blockIdx.x & 15) << 5;
    int tid = threadIdx.x;
    int warp = tid >> 5, lane = tid & 31;
    int g = lane >> 2, tg = lane & 3;
    int wm = warp >> 2, wn = warp & 3;

    uint32_t sb = (uint32_t)__cvta_generic_to_shared(sBp);
    const uint32_t* Bg = d_Rgp + (size_t)head * (64 * 512);
    #pragma unroll
    for (int i = 0; i < 32; i++) {
        int e = i * 256 + tid;
        int kp = e >> 7, c = (e & 127) * 4;
        cp_async16(sb + (uint32_t)(kp * 520 + c) * 4, Bg + (size_t)kp * 512 + c);
    }
    asm volatile("cp.async.commit_group;");
    for (int i = tid; i < 32 * 68; i += 256) sh_w[i] = 0;
    float cS[16], nS[16], mS[16];
    #pragma unroll
    for (int j = 0; j < 16; j++) { cS[j] = 0.f; nS[j] = 0.f; mS[j] = 0.f; }
    int hs_t = tid & 127;
    float gnw = __ldg(gng + head * 128 + hs_t);
    float gnbv = __ldg(gnb + head * 128 + hs_t);
    asm volatile("cp.async.wait_group 0;");
    __syncthreads();

    for (int t = 0; t < 12; t++) {
        float acc[16][4];
        #pragma unroll
        for (int j = 0; j < 16; j++)
            #pragma unroll
            for (int q = 0; q < 4; q++) acc[j][q] = 0.f;
        #pragma unroll
        for (int s = 0; s < 8; s++) {
            uint32_t a0 = sh_w[(wm * 16 + g)     * 68 + s * 8 + tg];
            uint32_t a1 = sh_w[(wm * 16 + 8 + g) * 68 + s * 8 + tg];
            uint32_t a2 = sh_w[(wm * 16 + g)     * 68 + s * 8 + tg + 4];
            uint32_t a3 = sh_w[(wm * 16 + 8 + g) * 68 + s * 8 + tg + 4];
            #pragma unroll
            for (int j = 0; j < 16; j++) {
                int c = wn * 128 + j * 8 + g;
                uint32_t b0v = sBp[(s * 8 + tg)     * 520 + c];
                uint32_t b1v = sBp[(s * 8 + tg + 4) * 520 + c];
                mma_bf16(acc[j], a0, a1, a2, a3, b0v, b1v);
            }
        }
        #pragma unroll
        for (int j = 0; j < 16; j++) {
            int c = wn * 128 + j * 8 + 2 * tg;
            int r = wm * 16 + g;
            s_rec[r * 516 + c]           = acc[j][0];
            s_rec[r * 516 + c + 1]       = acc[j][1];
            s_rec[(r + 8) * 516 + c]     = acc[j][2];
            s_rec[(r + 8) * 516 + c + 1] = acc[j][3];
        }
        __syncthreads();

        float hv16[16];
        #pragma unroll
        for (int it = 0; it < 16; it++) {
            int idx = it * 256 + tid;
            int bb = idx >> 7, hs = idx & 127;
            int b = b0 + bb;
            const __nv_bfloat16* gxp =
                d_gxh + (size_t)(b * 12 + t) * 4096 + head * 512;
            const float* rp = s_rec + bb * 516;
            float z_ = __bfloat162float(gxp[hs])       + rp[hs];
            float i_ = __bfloat162float(gxp[128 + hs]) + rp[128 + hs];
            float f_ = __bfloat162float(gxp[256 + hs]) + rp[256 + hs];
            float o_ = __bfloat162float(gxp[384 + hs]) + rp[384 + hs];
            float z  = tanhf(z_);
            float o  = sigmoidf_(o_);
            float mo = mS[it];
            float mn = fmaxf(f_ + mo, i_);
            float iv = expf(i_ - mn);
            float fv = expf(f_ + mo - mn);
            float cv = fv * cS[it] + iv * z;
            float nv = fv * nS[it] + iv;
            float hv = o * (cv / nv);
            cS[it] = cv; nS[it] = nv; mS[it] = mn;
            sh_h[bb * 136 + hs] = __float2bfloat16_rn(hv);
            hv16[it] = hv;
            float s = hv, ss = hv * hv;
            warp_reduce_2(s, ss);
            if (lane == 0) {
                gn_part[(it * 8 + warp) * 2]     = s;
                gn_part[(it * 8 + warp) * 2 + 1] = ss;
            }
        }
        __syncthreads();

        int wbase = (tid >> 7) * 4;
        #pragma unroll
        for (int it = 0; it < 16; it++) {
            float s = 0.f, ss = 0.f;
            #pragma unroll
            for (int q = 0; q < 4; q++) {
                s  += gn_part[(it * 8 + wbase + q) * 2];
                ss += gn_part[(it * 8 + wbase + q) * 2 + 1];
            }
            float mu = s * (1.0f / 128.0f);
            float rstd = rsqrtf(ss * (1.0f / 128.0f) - mu * mu + 1e-5f);
            int bb = (it << 1) + (tid >> 7);
            int b = b0 + bb;
            d_hnh[(size_t)(b * 12 + t) * 1024 + head * 128 + hs_t] =
                __float2bfloat16_rn((hv16[it] - mu) * rstd * gnw + gnbv);
        }
        __syncthreads();
    }
}

// ---------------- launch ----------------
extern "C" void kernel_launch(void* const* d_in, const int* in_sizes, int n_in,
                              void* d_out, int out_size) {
    const float* x       = (const float*)d_in[0];
    const float* ln_g    = (const float*)d_in[1];
    const float* ln_b    = (const float*)d_in[2];
    const float* fc1_w   = (const float*)d_in[3];
    const float* fc1_b   = (const float*)d_in[4];
    const float* fc2_w   = (const float*)d_in[5];
    const float* fc2_b   = (const float*)d_in[6];
    const float* conv1_w = (const float*)d_in[7];
    const float* conv1_b = (const float*)d_in[8];
    const float* conv2_w = (const float*)d_in[9];
    const float* conv2_b = (const float*)d_in[10];
    const float* xlg     = (const float*)d_in[11];
    const float* xlb     = (const float*)d_in[12];
    const float* Wg      = (const float*)d_in[13];
    const float* bg      = (const float*)d_in[14];
    const float* Rg      = (const float*)d_in[15];
    const float* gng     = (const float*)d_in[16];
    const float* gnb     = (const float*)d_in[17];
    const float* uplw    = (const float*)d_in[18];
    const float* uplb    = (const float*)d_in[19];
    const float* uprw    = (const float*)d_in[20];
    const float* uprb    = (const float*)d_in[21];
    const float* downw   = (const float*)d_in[22];
    const float* downb   = (const float*)d_in[23];
    float* out = (float*)d_out;

    cudaFuncSetAttribute(slstm_rec4,  cudaFuncAttributeMaxDynamicSharedMemorySize, 208896);
    cudaFuncSetAttribute(fused_front, cudaFuncAttributeMaxDynamicSharedMemorySize, 150240);
    cudaFuncSetAttribute(fused_tail,  cudaFuncAttributeMaxDynamicSharedMemorySize, 129648);

    float *p_xn, *p_xc, *p_x1, *p_y;
    __nv_bfloat16 *p_hnh, *p_uh;
    uint32_t *p_downp, *p_Wpair;
    cudaGetSymbolAddress((void**)&p_xn,    d_xn);
    cudaGetSymbolAddress((void**)&p_xc,    d_xc);
    cudaGetSymbolAddress((void**)&p_x1,    d_x1);
    cudaGetSymbolAddress((void**)&p_y,     d_y);
    cudaGetSymbolAddress((void**)&p_hnh,   d_hnh);
    cudaGetSymbolAddress((void**)&p_uh,    d_uh);
    cudaGetSymbolAddress((void**)&p_downp, d_downp);
    cudaGetSymbolAddress((void**)&p_Wpair, d_Wpair);

    pack_all<<<dim3(4, 512, 2), 256>>>(downw, uplw, uprw);
    pack_wq<<<dim3(16, 256), 256>>>(Wg);
    pack_rg<<<dim3(8, 16), 256>>>(Rg);

    // LN(x) -> fc1 -> fc2 -> LN -> fp8 quad   [fused per batch]
    fused_front<<<B_, 384, 150240>>>(x, ln_g, ln_b, fc1_w, fc1_b,
                                     fc2_w, fc2_b, xlg, xlb);
    // gx = xn2 @ Wg + bg  -> bf16  [fp8 e4m3 mma, 2x rate]
    gemm_fp8_gx<<<dim3(32, 48), 256>>>(bg);
    // sLSTM recurrence + fused GroupNorm -> d_hnh (bf16)
    slstm_rec4<<<128, 256, 208896>>>(gng, gnb);
    // u = gelu(hn@upl + uplb) * (hn@upr + uprb)
    gemm_bf16<3><<<dim3(16, 48), 256>>>(2048, 1024, p_hnh, p_Wpair, uplb,
                                        nullptr, uprb, nullptr, p_uh);
    // y = silu(xc) * (u @ down + downb + x1) + xn
    gemm_bf16<2><<<dim3(8, 48), 256>>>(1024, 1024, p_uh, p_downp, downb,
                                       p_xc, p_x1, p_xn, p_y);
    // conv12->48 + gelu + LN + conv48->12 + skip   [fused, fp32 throughout]
    fused_tail<<<B_, 512, 129648>>>(conv1_w, conv1_b, conv2_w, conv2_b,
                                    ln_g, ln_b, out);
}

// round 17
// speedup vs baseline: 1.0406x; 1.0406x over previous
#include <cuda_runtime.h>
#include <cuda_bf16.h>
#include <cmath>
#include <cstdint>

// ---------------- problem constants ----------------
static constexpr int B_   = 512;
static constexpr int T_   = 12;
static constexpr int E_   = 1024;
static constexpr int NH_  = 8;
static constexpr int HS_  = 128;
static constexpr int H_   = 1024;
static constexpr int G4_  = 4096;
static constexpr int BT_  = B_ * T_;        // 6144

// ---------------- scratch (device globals; no allocation) ----------------
__device__ float d_xn [BT_ * (size_t)E_];
__device__ float d_xc [BT_ * (size_t)E_];
__device__ float d_x1 [BT_ * (size_t)E_];
__device__ float d_y  [BT_ * (size_t)E_];
// bf16 operands
__device__ __nv_bfloat16 d_gxh [BT_ * (size_t)G4_];
__device__ __nv_bfloat16 d_xn2h[BT_ * (size_t)E_];
__device__ __nv_bfloat16 d_hnh [BT_ * (size_t)H_];
__device__ __nv_bfloat16 d_uh  [BT_ * (size_t)H_];
// pair-packed bf16 weights
__device__ uint32_t d_Wgp  [(size_t)512 * G4_];
__device__ uint32_t d_downp[(size_t)512 * E_];
__device__ uint32_t d_Wpair[(size_t)512 * 2048];
__device__ uint32_t d_Rgp  [(size_t)NH_ * 64 * 512];

// ---------------- helpers ----------------
__device__ __forceinline__ float gelu_exact(float x) {
    return 0.5f * x * (1.0f + erff(x * 0.70710678118654752440f));
}
__device__ __forceinline__ float sigmoidf_(float x) {
    return 1.0f / (1.0f + expf(-x));
}
__device__ __forceinline__ void cp_async16(uint32_t saddr, const void* g) {
    asm volatile("cp.async.cg.shared.global [%0], [%1], 16;" :: "r"(saddr), "l"(g));
}
__device__ __forceinline__ void mma_bf16(float* acc, uint32_t a0, uint32_t a1,
                                         uint32_t a2, uint32_t a3,
                                         uint32_t b0, uint32_t b1) {
    asm volatile(
        "mma.sync.aligned.m16n8k16.row.col.f32.bf16.bf16.f32 "
        "{%0,%1,%2,%3}, {%4,%5,%6,%7}, {%8,%9}, {%0,%1,%2,%3};"
        : "+f"(acc[0]), "+f"(acc[1]), "+f"(acc[2]), "+f"(acc[3])
        : "r"(a0), "r"(a1), "r"(a2), "r"(a3), "r"(b0), "r"(b1));
}
__device__ __forceinline__ void ldsm_x4(uint32_t* r, uint32_t saddr) {
    asm volatile("ldmatrix.sync.aligned.m8n8.x4.shared.b16 {%0,%1,%2,%3}, [%4];"
        : "=r"(r[0]), "=r"(r[1]), "=r"(r[2]), "=r"(r[3]) : "r"(saddr));
}
__device__ __forceinline__ void warp_reduce_2(float& s, float& ss) {
    #pragma unroll
    for (int o = 16; o; o >>= 1) {
        s  += __shfl_xor_sync(0xffffffffu, s,  o);
        ss += __shfl_xor_sync(0xffffffffu, ss, o);
    }
}

// ---------------- combined weight packs (one launch) ----------------
__global__ void pack_all(const float* __restrict__ Wg,
                         const float* __restrict__ downw,
                         const float* __restrict__ wl,
                         const float* __restrict__ wr) {
    int z = blockIdx.z;
    int kp = blockIdx.y;
    int n = blockIdx.x * 256 + threadIdx.x;
    if (z == 0) {
        __nv_bfloat162 h = __floats2bfloat162_rn(Wg[(size_t)(2 * kp) * 4096 + n],
                                                 Wg[(size_t)(2 * kp + 1) * 4096 + n]);
        d_Wgp[(size_t)kp * 4096 + n] = *reinterpret_cast<uint32_t*>(&h);
    } else if (z == 1) {
        if (blockIdx.x >= 4) return;
        __nv_bfloat162 h = __floats2bfloat162_rn(downw[(size_t)(2 * kp) * 1024 + n],
                                                 downw[(size_t)(2 * kp + 1) * 1024 + n]);
        d_downp[(size_t)kp * 1024 + n] = *reinterpret_cast<uint32_t*>(&h);
    } else {
        if (blockIdx.x >= 4) return;
        __nv_bfloat162 hl = __floats2bfloat162_rn(wl[(size_t)(2 * kp) * 1024 + n],
                                                  wl[(size_t)(2 * kp + 1) * 1024 + n]);
        __nv_bfloat162 hr = __floats2bfloat162_rn(wr[(size_t)(2 * kp) * 1024 + n],
                                                  wr[(size_t)(2 * kp + 1) * 1024 + n]);
        d_Wpair[(size_t)kp * 2048 + 2 * n]     = *reinterpret_cast<uint32_t*>(&hl);
        d_Wpair[(size_t)kp * 2048 + 2 * n + 1] = *reinterpret_cast<uint32_t*>(&hr);
    }
}
__global__ __launch_bounds__(256) void pack_rg(const float* __restrict__ Rg) {
    __shared__ float tile[32][129];
    int head = blockIdx.x;
    int g0 = blockIdx.y * 32;
    int tid = threadIdx.x;
    #pragma unroll
    for (int i = 0; i < 16; i++) {
        int e = i * 256 + tid;
        int r = e >> 7, c = e & 127;
        tile[r][c] = Rg[((size_t)(head * 512 + g0 + r)) * 128 + c];
    }
    __syncthreads();
    #pragma unroll
    for (int i = 0; i < 8; i++) {
        int e = i * 256 + tid;
        int kp = e >> 5, gl = e & 31;
        __nv_bfloat162 h = __floats2bfloat162_rn(tile[gl][2 * kp], tile[gl][2 * kp + 1]);
        d_Rgp[((size_t)(head * 64 + kp)) * 512 + g0 + gl] =
            *reinterpret_cast<uint32_t*>(&h);
    }
}

// ---------------- fused front: LN(x) -> fc1 conv -> fc2 -> LN -> bf16 ----------------
// Vectorized conv loops: 4 output positions per step, float4+float2 taps.
__global__ __launch_bounds__(384) void fused_front(
    const float* __restrict__ x,
    const float* __restrict__ ln_g, const float* __restrict__ ln_b,
    const float* __restrict__ w1g, const float* __restrict__ b1g,
    const float* __restrict__ w2g, const float* __restrict__ b2g,
    const float* __restrict__ xlg, const float* __restrict__ xlb) {
    extern __shared__ float sm[];
    float* sxn = sm;                    // [12][1032], data at +1, halo zeros
    float* sxc = sxn + 12 * 1032;       // [12][1024]
    float* sx1 = sxc + 12 * 1024;       // [12][1024]
    float* sw1 = sx1 + 12 * 1024;       // 432
    float* sw2 = sw1 + 432;             // 144
    float* sb1 = sw2 + 144;             // 12
    float* sb2 = sb1 + 12;              // 12
    int b = blockIdx.x, tid = threadIdx.x, w = tid >> 5, lane = tid & 31;

    for (int i = tid; i < 432; i += 384) sw1[i] = w1g[i];
    if (tid < 144) sw2[tid] = w2g[tid];
    if (tid < 12) { sb1[tid] = b1g[tid]; sb2[tid] = b2g[tid]; }
    if (lane == 0) { sxn[w * 1032] = 0.f; sxn[w * 1032 + 1025] = 0.f; }

    size_t rbase = ((size_t)b * 12 + w) * 1024;
    const float* xr = x + rbase;
    float4 vals[8];
    float s = 0.f, ss = 0.f;
    #pragma unroll
    for (int j = 0; j < 8; j++) {
        float4 v = *reinterpret_cast<const float4*>(xr + lane * 4 + j * 128);
        vals[j] = v;
        s  += v.x + v.y + v.z + v.w;
        ss += v.x*v.x + v.y*v.y + v.z*v.z + v.w*v.w;
    }
    warp_reduce_2(s, ss);
    float mu = s * (1.0f / 1024.0f);
    float rstd = rsqrtf(ss * (1.0f / 1024.0f) - mu * mu + 1e-5f);
    #pragma unroll
    for (int j = 0; j < 8; j++) {
        int idx = lane * 4 + j * 128;
        float4 g = *reinterpret_cast<const float4*>(ln_g + idx);
        float4 bb = *reinterpret_cast<const float4*>(ln_b + idx);
        float4 v = vals[j], o;
        o.x = (v.x - mu) * rstd * g.x + bb.x;
        o.y = (v.y - mu) * rstd * g.y + bb.y;
        o.z = (v.z - mu) * rstd * g.z + bb.z;
        o.w = (v.w - mu) * rstd * g.w + bb.w;
        sxn[w * 1032 + 1 + idx] = o.x; sxn[w * 1032 + 2 + idx] = o.y;
        sxn[w * 1032 + 3 + idx] = o.z; sxn[w * 1032 + 4 + idx] = o.w;
        *reinterpret_cast<float4*>(d_xn + rbase + idx) = o;
    }
    __syncthreads();

    {   // fc1 conv: warp w -> channel w; 4 outputs per step
        int o = w;
        float wl[36];
        #pragma unroll
        for (int i = 0; i < 36; i++) wl[i] = sw1[o * 36 + i];
        float bo = sb1[o];
        #pragma unroll
        for (int j = 0; j < 8; j++) {
            int l = lane * 4 + j * 128;
            float a0 = bo, a1 = bo, a2 = bo, a3 = bo;
            #pragma unroll
            for (int c = 0; c < 12; c++) {
                const float* yp = sxn + c * 1032 + l;    // taps l-1..l+4
                float4 p = *reinterpret_cast<const float4*>(yp);
                float2 q = *reinterpret_cast<const float2*>(yp + 4);
                float w0 = wl[c*3], w1 = wl[c*3+1], w2 = wl[c*3+2];
                a0 += w0 * p.x + w1 * p.y + w2 * p.z;
                a1 += w0 * p.y + w1 * p.z + w2 * p.w;
                a2 += w0 * p.z + w1 * p.w + w2 * q.x;
                a3 += w0 * p.w + w1 * q.x + w2 * q.y;
            }
            float4 ov = make_float4(a0, a1, a2, a3);
            *reinterpret_cast<float4*>(sxc + o * 1024 + l) = ov;
            *reinterpret_cast<float4*>(d_xc + rbase + l) = ov;
        }
    }
    __syncthreads();

    {   // fc2 1x1; 4 outputs per step, float4 per channel row
        int o = w;
        float wl[12];
        #pragma unroll
        for (int c = 0; c < 12; c++) wl[c] = sw2[o * 12 + c];
        float bo = sb2[o];
        #pragma unroll
        for (int j = 0; j < 8; j++) {
            int l = lane * 4 + j * 128;
            float a0 = bo, a1 = bo, a2 = bo, a3 = bo;
            #pragma unroll
            for (int c = 0; c < 12; c++) {
                float4 p = *reinterpret_cast<const float4*>(sxc + c * 1024 + l);
                float wc = wl[c];
                a0 += wc * p.x; a1 += wc * p.y; a2 += wc * p.z; a3 += wc * p.w;
            }
            float4 ov = make_float4(a0, a1, a2, a3);
            *reinterpret_cast<float4*>(sx1 + o * 1024 + l) = ov;
            *reinterpret_cast<float4*>(d_x1 + rbase + l) = ov;
        }
    }
    __syncthreads();

    // LN2 -> bf16
    s = 0.f; ss = 0.f;
    #pragma unroll
    for (int j = 0; j < 8; j++) {
        float4 v = *reinterpret_cast<const float4*>(sx1 + w * 1024 + lane * 4 + j * 128);
        vals[j] = v;
        s  += v.x + v.y + v.z + v.w;
        ss += v.x*v.x + v.y*v.y + v.z*v.z + v.w*v.w;
    }
    warp_reduce_2(s, ss);
    mu = s * (1.0f / 1024.0f);
    rstd = rsqrtf(ss * (1.0f / 1024.0f) - mu * mu + 1e-5f);
    #pragma unroll
    for (int j = 0; j < 8; j++) {
        int idx = lane * 4 + j * 128;
        float4 g = *reinterpret_cast<const float4*>(xlg + idx);
        float4 bb = *reinterpret_cast<const float4*>(xlb + idx);
        float4 v = vals[j];
        __nv_bfloat162 h0 = __floats2bfloat162_rn((v.x - mu) * rstd * g.x + bb.x,
                                                  (v.y - mu) * rstd * g.y + bb.y);
        __nv_bfloat162 h1 = __floats2bfloat162_rn((v.z - mu) * rstd * g.z + bb.z,
                                                  (v.w - mu) * rstd * g.w + bb.w);
        uint2 pk = make_uint2(*reinterpret_cast<uint32_t*>(&h0),
                              *reinterpret_cast<uint32_t*>(&h1));
        *reinterpret_cast<uint2*>(d_xn2h + rbase + idx) = pk;
    }
}

// ---------------- fused tail: all-fp32, 3 chunks; vectorized Phase A ----------------
__global__ __launch_bounds__(512) void fused_tail(
    const float* __restrict__ w1g, const float* __restrict__ b1g,
    const float* __restrict__ w2g, const float* __restrict__ b2g,
    const float* __restrict__ ln_g, const float* __restrict__ ln_b,
    float* __restrict__ out) {
    extern __shared__ float sm[];
    float* sy  = sm;                   // [12][1032], data at +1, halo zeros
    float* szf = sy + 12 * 1032;       // [16][1032] fp32 chunk, data at +1
    float* sw1 = szf + 16 * 1032;      // 1728 (o,c,k)
    float* sw2 = sw1 + 1728;           // 1728 repacked (c,o,k)
    float* sb1 = sw2 + 1728;           // 48
    float* sb2 = sb1 + 48;             // 12
    int b = blockIdx.x, tid = threadIdx.x, w = tid >> 5, lane = tid & 31;

    for (int i = tid; i < 12 * 256; i += 512) {
        int c = i >> 8, q = (i & 255) * 4;
        float4 v = *reinterpret_cast<const float4*>(d_y + ((size_t)b * 12 + c) * 1024 + q);
        sy[c * 1032 + 1 + q]     = v.x;
        sy[c * 1032 + 1 + q + 1] = v.y;
        sy[c * 1032 + 1 + q + 2] = v.z;
        sy[c * 1032 + 1 + q + 3] = v.w;
    }
    if (tid < 12) { sy[tid * 1032] = 0.f; sy[tid * 1032 + 1025] = 0.f; }
    if (tid < 16) { szf[tid * 1032] = 0.f; szf[tid * 1032 + 1025] = 0.f; }
    for (int i = tid; i < 1728; i += 512) {
        sw1[i] = w1g[i];
        int o = i / 144, rem = i % 144;
        int c = rem / 3, k = rem % 3;
        sw2[c * 36 + o * 3 + k] = w2g[i];
    }
    if (tid < 48) sb1[tid] = b1g[tid];
    if (tid < 12) sb2[tid] = b2g[tid];
    __syncthreads();

    int l2 = tid * 2;
    float acc0[12], acc1[12];
    #pragma unroll
    for (int o = 0; o < 12; o++) { acc0[o] = 0.f; acc1[o] = 0.f; }

    for (int cc = 0; cc < 3; cc++) {
        int o = cc * 16 + w;
        float wl[36];
        #pragma unroll
        for (int i = 0; i < 36; i++) wl[i] = sw1[o * 36 + i];
        float bo = sb1[o];
        float vbuf[32];
        float s = 0.f, ss = 0.f;
        #pragma unroll
        for (int j = 0; j < 8; j++) {            // 4 outputs per step
            int l = lane * 4 + j * 128;
            float a0 = bo, a1 = bo, a2 = bo, a3 = bo;
            #pragma unroll
            for (int c = 0; c < 12; c++) {
                const float* yp = sy + c * 1032 + l;
                float4 p = *reinterpret_cast<const float4*>(yp);
                float2 q = *reinterpret_cast<const float2*>(yp + 4);
                float w0 = wl[c*3], w1 = wl[c*3+1], w2 = wl[c*3+2];
                a0 += w0 * p.x + w1 * p.y + w2 * p.z;
                a1 += w0 * p.y + w1 * p.z + w2 * p.w;
                a2 += w0 * p.z + w1 * p.w + w2 * q.x;
                a3 += w0 * p.w + w1 * q.x + w2 * q.y;
            }
            float v0 = gelu_exact(a0), v1 = gelu_exact(a1);
            float v2 = gelu_exact(a2), v3 = gelu_exact(a3);
            vbuf[j*4] = v0; vbuf[j*4+1] = v1; vbuf[j*4+2] = v2; vbuf[j*4+3] = v3;
            s += v0 + v1 + v2 + v3;
            ss += v0*v0 + v1*v1 + v2*v2 + v3*v3;
        }
        warp_reduce_2(s, ss);
        float mu = s * (1.0f / 1024.0f);
        float rstd = rsqrtf(ss * (1.0f / 1024.0f) - mu * mu + 1e-5f);
        #pragma unroll
        for (int j = 0; j < 8; j++) {
            int l = lane * 4 + j * 128;
            #pragma unroll
            for (int k = 0; k < 4; k++)
                szf[w * 1032 + 1 + l + k] =
                    (vbuf[j*4+k] - mu) * rstd * __ldg(ln_g + l + k) + __ldg(ln_b + l + k);
        }
        __syncthreads();

        for (int c16 = 0; c16 < 16; c16++) {
            int c = cc * 16 + c16;
            const float* zr = szf + c16 * 1032 + l2;
            float2 p0 = *reinterpret_cast<const float2*>(zr);
            float2 p1 = *reinterpret_cast<const float2*>(zr + 2);
            float h0 = p0.x, h1 = p0.y, h2 = p1.x, h3 = p1.y;
            const float* wr = sw2 + c * 36;
            #pragma unroll
            for (int o2 = 0; o2 < 12; o2++) {
                float w0 = wr[o2*3], w1 = wr[o2*3+1], w2v = wr[o2*3+2];
                acc0[o2] += w0 * h0 + w1 * h1 + w2v * h2;
                acc1[o2] += w0 * h1 + w1 * h2 + w2v * h3;
            }
        }
        __syncthreads();
    }

    #pragma unroll
    for (int o = 0; o < 12; o++) {
        size_t idx = ((size_t)b * 12 + o) * 1024 + l2;
        float2 sk = *reinterpret_cast<const float2*>(d_xn + idx);
        float2 ov;
        ov.x = acc0[o] + sb2[o] + sk.x;
        ov.y = acc1[o] + sb2[o] + sk.y;
        *reinterpret_cast<float2*>(out + idx) = ov;
    }
}

// ---------------- bf16 tensor-core GEMM: 3-stage cp.async + ldmatrix A ----------------
// MODE 2: C(fp32) = silu(aux0) * (acc + bias + aux1) + aux2
// MODE 3: interleaved pair: C(bf16)[r][c/2] = gelu(accL+bias) * (accR+aux1)
// MODE 4: C(bf16) = acc + bias
template<int MODE>
__global__ __launch_bounds__(256) void gemm_bf16(int N, int K,
                                                 const __nv_bfloat16* __restrict__ A,
                                                 const uint32_t* __restrict__ Bp,
                                                 const float* __restrict__ bias,
                                                 const float* __restrict__ aux0,
                                                 const float* __restrict__ aux1,
                                                 const float* __restrict__ aux2,
                                                 void* __restrict__ Cout) {
    __shared__ uint32_t As[3][128 * 20];
    __shared__ uint32_t Bs[3][16 * 136];
    int tid = threadIdx.x;
    int warp = tid >> 5, lane = tid & 31;
    int g = lane >> 2, tg = lane & 3;
    int warpM = warp >> 2, warpN = warp & 3;
    int row0 = blockIdx.y * 128, col0 = blockIdx.x * 128;

    uint32_t asb = (uint32_t)__cvta_generic_to_shared(&As[0][0]);
    uint32_t bsb = (uint32_t)__cvta_generic_to_shared(&Bs[0][0]);

    float acc[4][4][4];
    #pragma unroll
    for (int m = 0; m < 4; m++)
        #pragma unroll
        for (int n = 0; n < 4; n++)
            #pragma unroll
            for (int q = 0; q < 4; q++) acc[m][n][q] = 0.f;

    const int nt = K >> 5;

    auto load_tile = [&](int it, int buf) {
        int k0 = it << 5;
        int kp0 = it << 4;
        #pragma unroll
        for (int i = 0; i < 2; i++) {
            int e = i * 256 + tid;
            int r = e >> 2, ch = e & 3;
            cp_async16(asb + (uint32_t)(buf * 128 * 20 + r * 20 + ch * 4) * 4,
                       A + (size_t)(row0 + r) * K + k0 + ch * 8);
        }
        #pragma unroll
        for (int i = 0; i < 2; i++) {
            int e = i * 256 + tid;
            int kp = e >> 5, c = (e & 31) * 4;
            cp_async16(bsb + (uint32_t)(buf * 16 * 136 + kp * 136 + c) * 4,
                       Bp + (size_t)(kp0 + kp) * N + col0 + c);
        }
        asm volatile("cp.async.commit_group;");
    };

    load_tile(0, 0);
    load_tile(1, 1);

    int arow = warpM * 64;
    int bcol = warpN * 32 + g;
    int lseg = lane >> 3;
    int a_row = (lseg & 1) * 8 + (lane & 7);
    int a_kw  = (lseg >> 1) * 4;

    for (int it = 0; it < nt; it++) {
        int buf = it - (it / 3) * 3;
        asm volatile("cp.async.wait_group 1;");
        __syncthreads();
        if (it + 2 < nt) {
            int buf2 = (it + 2) - ((it + 2) / 3) * 3;
            load_tile(it + 2, buf2);
        } else {
            asm volatile("cp.async.commit_group;");
        }
        uint32_t a_base = asb + (uint32_t)(buf * 128 * 20) * 4;
        const uint32_t* Bb = &Bs[buf][0];
        #pragma unroll
        for (int s = 0; s < 2; s++) {
            uint32_t af[4][4];
            #pragma unroll
            for (int m = 0; m < 4; m++) {
                uint32_t sa = a_base +
                    (uint32_t)((arow + m * 16 + a_row) * 20 + s * 8 + a_kw) * 4;
                ldsm_x4(af[m], sa);
            }
            uint32_t bf[4][2];
            #pragma unroll
            for (int n = 0; n < 4; n++) {
                int c = bcol + n * 8;
                bf[n][0] = Bb[(s * 8 + tg)     * 136 + c];
                bf[n][1] = Bb[(s * 8 + tg + 4) * 136 + c];
            }
            #pragma unroll
            for (int m = 0; m < 4; m++)
                #pragma unroll
                for (int n = 0; n < 4; n++)
                    mma_bf16(acc[m][n], af[m][0], af[m][1], af[m][2], af[m][3],
                             bf[n][0], bf[n][1]);
        }
    }

    __syncthreads();
    #pragma unroll
    for (int m = 0; m < 4; m++) {
        int r = row0 + warpM * 64 + m * 16 + g;
        #pragma unroll
        for (int n = 0; n < 4; n++) {
            int c = col0 + warpN * 32 + n * 8 + 2 * tg;
            #pragma unroll
            for (int half = 0; half < 2; half++) {
                int rr = r + half * 8;
                float a0 = acc[m][n][half * 2 + 0];
                float a1 = acc[m][n][half * 2 + 1];
                if (MODE == 3) {
                    int j = c >> 1;
                    float l  = a0 + bias[j];
                    float rv = a1 + aux1[j];
                    ((__nv_bfloat16*)Cout)[(size_t)rr * (N >> 1) + j] =
                        __float2bfloat16_rn(gelu_exact(l) * rv);
                } else if (MODE == 4) {
                    size_t i0 = (size_t)rr * N + c;
                    __nv_bfloat162 hh = __floats2bfloat162_rn(a0 + bias[c],
                                                              a1 + bias[c + 1]);
                    *reinterpret_cast<uint32_t*>((__nv_bfloat16*)Cout + i0) =
                        *reinterpret_cast<uint32_t*>(&hh);
                } else {
                    size_t i0 = (size_t)rr * N + c;
                    float v0 = a0 + bias[c];
                    float v1 = a1 + bias[c + 1];
                    if (MODE == 2) {
                        float x0 = aux0[i0], x1v = aux0[i0 + 1];
                        v0 = x0  * sigmoidf_(x0)  * (v0 + aux1[i0])     + aux2[i0];
                        v1 = x1v * sigmoidf_(x1v) * (v1 + aux1[i0 + 1]) + aux2[i0 + 1];
                    }
                    *reinterpret_cast<float2*>((float*)Cout + i0) = make_float2(v0, v1);
                }
            }
        }
    }
}

// ---------------- sLSTM recurrence v4: fused GroupNorm -> d_hnh ----------------
__global__ __launch_bounds__(256) void slstm_rec4(const float* __restrict__ gng,
                                                  const float* __restrict__ gnb) {
    extern __shared__ uint32_t smw[];
    uint32_t* sBp = smw;
    float* s_rec = (float*)(smw + 64 * 520);
    uint32_t* sh_w = (uint32_t*)(s_rec + 32 * 516);
    float* gn_part = (float*)(sh_w + 32 * 68);
    __nv_bfloat16* sh_h = (__nv_bfloat16*)sh_w;

    int head = blockIdx.x >> 4;
    int b0 = (blockIdx.x & 15) << 5;
    int tid = threadIdx.x;
    int warp = tid >> 5, lane = tid & 31;
    int g = lane >> 2, tg = lane & 3;
    int wm = warp >> 2, wn = warp & 3;

    uint32_t sb = (uint32_t)__cvta_generic_to_shared(sBp);
    const uint32_t* Bg = d_Rgp + (size_t)head * (64 * 512);
    #pragma unroll
    for (int i = 0; i < 32; i++) {
        int e = i * 256 + tid;
        int kp = e >> 7, c = (e & 127) * 4;
        cp_async16(sb + (uint32_t)(kp * 520 + c) * 4, Bg + (size_t)kp * 512 + c);
    }
    asm volatile("cp.async.commit_group;");
    for (int i = tid; i < 32 * 68; i += 256) sh_w[i] = 0;
    float cS[16], nS[16], mS[16];
    #pragma unroll
    for (int j = 0; j < 16; j++) { cS[j] = 0.f; nS[j] = 0.f; mS[j] = 0.f; }
    int hs_t = tid & 127;
    float gnw = __ldg(gng + head * 128 + hs_t);
    float gnbv = __ldg(gnb + head * 128 + hs_t);
    asm volatile("cp.async.wait_group 0;");
    __syncthreads();

    for (int t = 0; t < 12; t++) {
        float acc[16][4];
        #pragma unroll
        for (int j = 0; j < 16; j++)
            #pragma unroll
            for (int q = 0; q < 4; q++) acc[j][q] = 0.f;
        #pragma unroll
        for (int s = 0; s < 8; s++) {
            uint32_t a0 = sh_w[(wm * 16 + g)     * 68 + s * 8 + tg];
            uint32_t a1 = sh_w[(wm * 16 + 8 + g) * 68 + s * 8 + tg];
            uint32_t a2 = sh_w[(wm * 16 + g)     * 68 + s * 8 + tg + 4];
            uint32_t a3 = sh_w[(wm * 16 + 8 + g) * 68 + s * 8 + tg + 4];
            #pragma unroll
            for (int j = 0; j < 16; j++) {
                int c = wn * 128 + j * 8 + g;
                uint32_t b0v = sBp[(s * 8 + tg)     * 520 + c];
                uint32_t b1v = sBp[(s * 8 + tg + 4) * 520 + c];
                mma_bf16(acc[j], a0, a1, a2, a3, b0v, b1v);
            }
        }
        #pragma unroll
        for (int j = 0; j < 16; j++) {
            int c = wn * 128 + j * 8 + 2 * tg;
            int r = wm * 16 + g;
            s_rec[r * 516 + c]           = acc[j][0];
            s_rec[r * 516 + c + 1]       = acc[j][1];
            s_rec[(r + 8) * 516 + c]     = acc[j][2];
            s_rec[(r + 8) * 516 + c + 1] = acc[j][3];
        }
        __syncthreads();

        float hv16[16];
        #pragma unroll
        for (int it = 0; it < 16; it++) {
            int idx = it * 256 + tid;
            int bb = idx >> 7, hs = idx & 127;
            int b = b0 + bb;
            const __nv_bfloat16* gxp =
                d_gxh + (size_t)(b * 12 + t) * 4096 + head * 512;
            const float* rp = s_rec + bb * 516;
            float z_ = __bfloat162float(gxp[hs])       + rp[hs];
            float i_ = __bfloat162float(gxp[128 + hs]) + rp[128 + hs];
            float f_ = __bfloat162float(gxp[256 + hs]) + rp[256 + hs];
            float o_ = __bfloat162float(gxp[384 + hs]) + rp[384 + hs];
            float z  = tanhf(z_);
            float o  = sigmoidf_(o_);
            float mo = mS[it];
            float mn = fmaxf(f_ + mo, i_);
            float iv = expf(i_ - mn);
            float fv = expf(f_ + mo - mn);
            float cv = fv * cS[it] + iv * z;
            float nv = fv * nS[it] + iv;
            float hv = o * (cv / nv);
            cS[it] = cv; nS[it] = nv; mS[it] = mn;
            sh_h[bb * 136 + hs] = __float2bfloat16_rn(hv);
            hv16[it] = hv;
            float s = hv, ss = hv * hv;
            warp_reduce_2(s, ss);
            if (lane == 0) {
                gn_part[(it * 8 + warp) * 2]     = s;
                gn_part[(it * 8 + warp) * 2 + 1] = ss;
            }
        }
        __syncthreads();

        int wbase = (tid >> 7) * 4;
        #pragma unroll
        for (int it = 0; it < 16; it++) {
            float s = 0.f, ss = 0.f;
            #pragma unroll
            for (int q = 0; q < 4; q++) {
                s  += gn_part[(it * 8 + wbase + q) * 2];
                ss += gn_part[(it * 8 + wbase + q) * 2 + 1];
            }
            float mu = s * (1.0f / 128.0f);
            float rstd = rsqrtf(ss * (1.0f / 128.0f) - mu * mu + 1e-5f);
            int bb = (it << 1) + (tid >> 7);
            int b = b0 + bb;
            d_hnh[(size_t)(b * 12 + t) * 1024 + head * 128 + hs_t] =
                __float2bfloat16_rn((hv16[it] - mu) * rstd * gnw + gnbv);
        }
        __syncthreads();
    }
}

// ---------------- launch ----------------
extern "C" void kernel_launch(void* const* d_in, const int* in_sizes, int n_in,
                              void* d_out, int out_size) {
    const float* x       = (const float*)d_in[0];
    const float* ln_g    = (const float*)d_in[1];
    const float* ln_b    = (const float*)d_in[2];
    const float* fc1_w   = (const float*)d_in[3];
    const float* fc1_b   = (const float*)d_in[4];
    const float* fc2_w   = (const float*)d_in[5];
    const float* fc2_b   = (const float*)d_in[6];
    const float* conv1_w = (const float*)d_in[7];
    const float* conv1_b = (const float*)d_in[8];
    const float* conv2_w = (const float*)d_in[9];
    const float* conv2_b = (const float*)d_in[10];
    const float* xlg     = (const float*)d_in[11];
    const float* xlb     = (const float*)d_in[12];
    const float* Wg      = (const float*)d_in[13];
    const float* bg      = (const float*)d_in[14];
    const float* Rg      = (const float*)d_in[15];
    const float* gng     = (const float*)d_in[16];
    const float* gnb     = (const float*)d_in[17];
    const float* uplw    = (const float*)d_in[18];
    const float* uplb    = (const float*)d_in[19];
    const float* uprw    = (const float*)d_in[20];
    const float* uprb    = (const float*)d_in[21];
    const float* downw   = (const float*)d_in[22];
    const float* downb   = (const float*)d_in[23];
    float* out = (float*)d_out;

    cudaFuncSetAttribute(slstm_rec4,  cudaFuncAttributeMaxDynamicSharedMemorySize, 208896);
    cudaFuncSetAttribute(fused_front, cudaFuncAttributeMaxDynamicSharedMemorySize, 150240);
    cudaFuncSetAttribute(fused_tail,  cudaFuncAttributeMaxDynamicSharedMemorySize, 129648);

    float *p_xn, *p_xc, *p_x1, *p_y;
    __nv_bfloat16 *p_gxh, *p_xn2h, *p_hnh, *p_uh;
    uint32_t *p_Wgp, *p_downp, *p_Wpair;
    cudaGetSymbolAddress((void**)&p_xn,    d_xn);
    cudaGetSymbolAddress((void**)&p_xc,    d_xc);
    cudaGetSymbolAddress((void**)&p_x1,    d_x1);
    cudaGetSymbolAddress((void**)&p_y,     d_y);
    cudaGetSymbolAddress((void**)&p_gxh,   d_gxh);
    cudaGetSymbolAddress((void**)&p_xn2h,  d_xn2h);
    cudaGetSymbolAddress((void**)&p_hnh,   d_hnh);
    cudaGetSymbolAddress((void**)&p_uh,    d_uh);
    cudaGetSymbolAddress((void**)&p_Wgp,   d_Wgp);
    cudaGetSymbolAddress((void**)&p_downp, d_downp);
    cudaGetSymbolAddress((void**)&p_Wpair, d_Wpair);

    pack_all<<<dim3(16, 512, 3), 256>>>(Wg, downw, uplw, uprw);
    pack_rg<<<dim3(8, 16), 256>>>(Rg);

    // LN(x) -> fc1 -> fc2 -> LN -> bf16   [fused per batch, vectorized]
    fused_front<<<B_, 384, 150240>>>(x, ln_g, ln_b, fc1_w, fc1_b,
                                     fc2_w, fc2_b, xlg, xlb);
    // gx = xn2 @ Wg + bg  -> bf16
    gemm_bf16<4><<<dim3(32, 48), 256>>>(4096, 1024, p_xn2h, p_Wgp, bg,
                                        nullptr, nullptr, nullptr, p_gxh);
    // sLSTM recurrence + fused GroupNorm -> d_hnh (bf16)
    slstm_rec4<<<128, 256, 208896>>>(gng, gnb);
    // u = gelu(hn@upl + uplb) * (hn@upr + uprb)
    gemm_bf16<3><<<dim3(16, 48), 256>>>(2048, 1024, p_hnh, p_Wpair, uplb,
                                        nullptr, uprb, nullptr, p_uh);
    // y = silu(xc) * (u @ down + downb + x1) + xn
    gemm_bf16<2><<<dim3(8, 48), 256>>>(1024, 1024, p_uh, p_downp, downb,
                                       p_xc, p_x1, p_xn, p_y);
    // conv12->48 + gelu + LN + conv48->12 + skip   [fused, vectorized Phase A]
    fused_tail<<<B_, 512, 129648>>>(conv1_w, conv1_b, conv2_w, conv2_b,
                                    ln_g, ln_b, out);
}